// round 7
// baseline (speedup 1.0000x reference)
#include <cuda_runtime.h>
#include <cuda_fp16.h>

// GaussianLayer: 2D Gaussian "same" conv (25x25, center tap zeroed) over
// src (4,512,512,21) NHWC fp32.  dst = g_y * (g_x * src) - src.
// Round 7: pass_h channel-pair FFMA2 (no pack MOVs, fewer LDG/ST);
//          pass_v 8-column x 8-row tiles with LDG.128 window loads.

#define BATCH 4
#define HH    512
#define WW    512
#define CC    21
#define RR    12
#define TAPS  25
#define ROWF  (WW * CC)          /* 10752 floats per (b,y) row */
#define IMGF  (HH * ROWF)
#define TOTALF (BATCH * IMGF)    /* 22,020,096 */

typedef unsigned long long u64;

// fp16 scratch, 16B-aligned (uint4 accesses in pass_v)
__device__ __align__(16) __half g_tmp[TOTALF];   // 44 MB

__device__ __forceinline__ u64 pack2(float lo, float hi) {
    u64 r; asm("mov.b64 %0, {%1, %2};" : "=l"(r) : "f"(lo), "f"(hi)); return r;
}
__device__ __forceinline__ void fma2(u64& d, u64 a, u64 b) {
    asm("fma.rn.f32x2 %0, %1, %2, %0;" : "+l"(d) : "l"(a), "l"(b));
}
__device__ __forceinline__ float2 unpack2(u64 v) {
    float2 f; asm("mov.b64 {%0, %1}, %2;" : "=f"(f.x), "=f"(f.y) : "l"(v)); return f;
}

// 13 symmetric 1D weights from row RR of the 2D kernel; center weight = 1
// (the zeroed 2D center tap is handled by subtracting src at the end).
__device__ __forceinline__ void load_weights(const float* __restrict__ k, u64* W2) {
#pragma unroll
    for (int j = 0; j < 12; ++j) {
        float w = __ldg(k + RR * TAPS + j);
        W2[j] = pack2(w, w);
    }
    W2[12] = pack2(1.0f, 1.0f);
}

// ---------------- Pass 1: horizontal -----------------------------------
// Per (b,y) row: 352 threads (= 11 warps worth per row, 352 % 32 == 0).
//   rem <  320 : pair unit  — channels (2u, 2u+1), 16 x-outputs, FFMA2 over
//                natural float2 channel pairs (no pack MOVs).
//   rem >= 320 : scalar unit — channel 20, 16 x-outputs (round-6 path).
// Pair and scalar units live in different warps (320 = 10 warps).
#define PER_ROW_H 352

__global__ void __launch_bounds__(256) pass_h_kernel(const float* __restrict__ src,
                                                     const float* __restrict__ k) {
    int tid = blockIdx.x * 256 + threadIdx.x;
    int row = tid / PER_ROW_H;                  // b*HH + y
    int rem = tid - row * PER_ROW_H;

    const float* rp = src   + (size_t)row * ROWF;
    __half*      op = g_tmp + (size_t)row * ROWF;

    u64 W2[13];
    load_weights(k, W2);

    if (rem < 320) {
        // ---- channel-pair path ----
        int xg = rem / 10;
        int u  = rem - xg * 10;
        int c0 = 2 * u;
        int x0 = xg * 16;
        int base = x0 * CC + c0;                // even flat index

        u64 A[16];
#pragma unroll
        for (int m = 0; m < 16; ++m) A[m] = 0ull;

        if (x0 >= RR && x0 + 27 < WW) {
#pragma unroll
            for (int s = 0; s < 40; ++s) {
                int flat = base + (s - RR) * CC;
                u64 P;
                if ((s & 1) == 0) {             // flat even -> LDG.64
                    float2 t = *(const float2*)(rp + flat);
                    P = pack2(t.x, t.y);
                } else {                        // flat odd -> 2x LDG.32
                    P = pack2(rp[flat], rp[flat + 1]);
                }
#pragma unroll
                for (int m = 0; m < 16; ++m) {
                    int n = s - m;
                    if (n >= 0 && n < TAPS)
                        fma2(A[m], W2[n <= RR ? n : 24 - n], P);
                }
            }
        } else {
#pragma unroll
            for (int s = 0; s < 40; ++s) {
                int xin = x0 - RR + s;
                int flat = base + (s - RR) * CC;
                u64 P = 0ull;
                if (xin >= 0 && xin < WW) {
                    if ((s & 1) == 0) {
                        float2 t = *(const float2*)(rp + flat);
                        P = pack2(t.x, t.y);
                    } else {
                        P = pack2(rp[flat], rp[flat + 1]);
                    }
                }
#pragma unroll
                for (int m = 0; m < 16; ++m) {
                    int n = s - m;
                    if (n >= 0 && n < TAPS)
                        fma2(A[m], W2[n <= RR ? n : 24 - n], P);
                }
            }
        }

#pragma unroll
        for (int m = 0; m < 16; ++m) {
            float2 o = unpack2(A[m]);
            int flat = base + m * CC;           // even iff m even
            __half h0 = __float2half_rn(o.x);
            __half h1 = __float2half_rn(o.y);
            if ((m & 1) == 0) {
                __half2 hh; hh.x = h0; hh.y = h1;
                *(__half2*)(op + flat) = hh;    // STS... STG.32
            } else {
                op[flat]     = h0;
                op[flat + 1] = h1;
            }
        }
    } else {
        // ---- scalar path: channel 20 ----
        int xg = rem - 320;                     // 0..31
        int x0 = xg * 16;
        int base = x0 * CC + 20;

        float v[40];
        if (x0 >= RR && x0 + 27 < WW) {
#pragma unroll
            for (int s = 0; s < 40; ++s)
                v[s] = rp[base + (s - RR) * CC];
        } else {
#pragma unroll
            for (int s = 0; s < 40; ++s) {
                int xin = x0 - RR + s;
                v[s] = (xin >= 0 && xin < WW) ? rp[base + (s - RR) * CC] : 0.0f;
            }
        }

        u64 A[8];
#pragma unroll
        for (int m = 0; m < 8; ++m) A[m] = 0ull;
#pragma unroll
        for (int i = 0; i < 39; ++i) {
            u64 P = pack2(v[i], v[i + 1]);
#pragma unroll
            for (int m = 0; m < 8; ++m) {
                int n = i - 2 * m;
                if (n >= 0 && n < TAPS)
                    fma2(A[m], W2[n <= RR ? n : 24 - n], P);
            }
        }
#pragma unroll
        for (int m = 0; m < 8; ++m) {
            float2 o = unpack2(A[m]);
            op[base + (2 * m)     * CC] = __float2half_rn(o.x);
            op[base + (2 * m + 1) * CC] = __float2half_rn(o.y);
        }
    }
}

// ---------------- Pass 2: vertical + subtract src -----------------------
// Thread = 8 consecutive flat columns (one uint4 of fp16) x 8 y rows.
// Window: 32 rows of LDG.128; accums 8 rows x 4 column-pairs of f32x2.
__global__ void __launch_bounds__(256) pass_v_kernel(const float* __restrict__ src,
                                                     const float* __restrict__ k,
                                                     float* __restrict__ dst) {
    const int OCTS  = ROWF / 8;                 // 1344 column-octets per row
    const int PER_B = (HH / 8) * OCTS;          // 86,016 threads per batch
    int tid = blockIdx.x * 256 + threadIdx.x;

    int b   = tid / PER_B;
    int rem = tid - b * PER_B;
    int yg  = rem / OCTS;
    int q   = rem - yg * OCTS;
    int y0  = yg * 8;
    int f0  = q * 8;

    size_t off = (size_t)b * IMGF + f0;
    const __half* tp = g_tmp + off;
    const float*  sp = src + off;
    float*        dp = dst + off;

    u64 W2[13];
    load_weights(k, W2);

    u64 A[8][4];
#pragma unroll
    for (int m = 0; m < 8; ++m)
#pragma unroll
        for (int p = 0; p < 4; ++p) A[m][p] = 0ull;

    bool interior = (y0 >= RR) && (y0 + 19 < HH);

#pragma unroll
    for (int s = 0; s < 32; ++s) {
        int yin = y0 - RR + s;
        u64 P[4];
        if (interior || (yin >= 0 && yin < HH)) {
            uint4 qv = *(const uint4*)(tp + (size_t)yin * ROWF);
            const __half2* h2 = (const __half2*)&qv;
#pragma unroll
            for (int p = 0; p < 4; ++p) {
                float2 f = __half22float2(h2[p]);
                P[p] = pack2(f.x, f.y);
            }
        } else {
#pragma unroll
            for (int p = 0; p < 4; ++p) P[p] = 0ull;
        }
#pragma unroll
        for (int m = 0; m < 8; ++m) {
            int n = s - m;
            if (n >= 0 && n < TAPS) {
                u64 w = W2[n <= RR ? n : 24 - n];
#pragma unroll
                for (int p = 0; p < 4; ++p)
                    fma2(A[m][p], w, P[p]);
            }
        }
    }

#pragma unroll
    for (int m = 0; m < 8; ++m) {
        const float* s_row = sp + (size_t)(y0 + m) * ROWF;
        float*       d_row = dp + (size_t)(y0 + m) * ROWF;
        float4 s0 = *(const float4*)(s_row);
        float4 s1 = *(const float4*)(s_row + 4);
        float2 o0 = unpack2(A[m][0]);
        float2 o1 = unpack2(A[m][1]);
        float2 o2 = unpack2(A[m][2]);
        float2 o3 = unpack2(A[m][3]);
        float4 r0, r1;
        r0.x = o0.x - s0.x;  r0.y = o0.y - s0.y;
        r0.z = o1.x - s0.z;  r0.w = o1.y - s0.w;
        r1.x = o2.x - s1.x;  r1.y = o2.y - s1.y;
        r1.z = o3.x - s1.z;  r1.w = o3.y - s1.w;
        *(float4*)(d_row)     = r0;
        *(float4*)(d_row + 4) = r1;
    }
}

extern "C" void kernel_launch(void* const* d_in, const int* in_sizes, int n_in,
                              void* d_out, int out_size) {
    const float* src = (const float*)d_in[0];
    const float* k   = (const float*)d_in[1];
    float*       dst = (float*)d_out;

    int nthreads_h = BATCH * HH * PER_ROW_H;              // 720,896
    pass_h_kernel<<<nthreads_h / 256, 256>>>(src, k);

    int nthreads_v = BATCH * (HH / 8) * (ROWF / 8);       // 344,064
    pass_v_kernel<<<nthreads_v / 256, 256>>>(src, k, dst);
}

// round 9
// speedup vs baseline: 1.0560x; 1.0560x over previous
#include <cuda_runtime.h>
#include <cuda_fp16.h>

// GaussianLayer: 2D Gaussian "same" conv (25x25, center tap zeroed) over
// src (4,512,512,21) NHWC fp32.  dst = g_y * (g_x * src) - src.
// Round 8: revert to round-6 structure (front-batched register windows).
// pass_v adds streaming cache hints (__ldcs/__stcs) for the stream-once
// src/dst traffic (protects g_tmp L2 residency) and launch_bounds(256,5)
// for 5 CTAs/SM occupancy.

#define BATCH 4
#define HH    512
#define WW    512
#define CC    21
#define RR    12
#define TAPS  25
#define ROWF  (WW * CC)          /* 10752 floats per (b,y) row */
#define IMGF  (HH * ROWF)
#define TOTALF (BATCH * IMGF)    /* 22,020,096 */

typedef unsigned long long u64;

__device__ __half g_tmp[TOTALF];   // 44 MB fp16 scratch (L2-resident for pass_v)

__device__ __forceinline__ u64 pack2(float lo, float hi) {
    u64 r; asm("mov.b64 %0, {%1, %2};" : "=l"(r) : "f"(lo), "f"(hi)); return r;
}
__device__ __forceinline__ void fma2(u64& d, u64 a, u64 b) {
    asm("fma.rn.f32x2 %0, %1, %2, %0;" : "+l"(d) : "l"(a), "l"(b));
}
__device__ __forceinline__ float2 unpack2(u64 v) {
    float2 f; asm("mov.b64 {%0, %1}, %2;" : "=f"(f.x), "=f"(f.y) : "l"(v)); return f;
}

// 13 symmetric 1D weights from row RR of the 2D kernel; center weight = 1
// (the zeroed 2D center tap is handled by subtracting src at the end).
__device__ __forceinline__ void load_weights(const float* __restrict__ k, u64* W2) {
#pragma unroll
    for (int j = 0; j < 12; ++j) {
        float w = __ldg(k + RR * TAPS + j);
        W2[j] = pack2(w, w);
    }
    W2[12] = pack2(1.0f, 1.0f);
}

// ---------------- Pass 1: horizontal. 16 adjacent x outputs per thread, -----
// scalar sliding window of 40 loads (front-batched, L1-served), FFMA2 pairs.
__global__ void __launch_bounds__(256) pass_h_kernel(const float* __restrict__ src,
                                                     const float* __restrict__ k) {
    const int PER_ROW = (WW / 16) * CC;             // 672 threads per (b,y) row
    int tid = blockIdx.x * 256 + threadIdx.x;       // grid sized exactly

    int row = tid / PER_ROW;                        // b*HH + y
    int rem = tid - row * PER_ROW;
    int xg  = rem / CC;
    int c   = rem - xg * CC;
    int x0  = xg * 16;

    const float* rp = src   + (size_t)row * ROWF;
    __half*      op = g_tmp + (size_t)row * ROWF;
    int base = x0 * CC + c;

    u64 W2[13];
    load_weights(k, W2);

    float v[40];
    if (x0 >= RR && x0 + 27 < WW) {                 // interior: xin in range
#pragma unroll
        for (int s = 0; s < 40; ++s)
            v[s] = rp[base + (s - RR) * CC];
    } else {
#pragma unroll
        for (int s = 0; s < 40; ++s) {
            int xin = x0 - RR + s;
            v[s] = (xin >= 0 && xin < WW) ? rp[base + (s - RR) * CC] : 0.0f;
        }
    }

    // A[m] accumulates outputs (x0+2m, x0+2m+1), m = 0..7
    u64 A[8] = {0ull, 0ull, 0ull, 0ull, 0ull, 0ull, 0ull, 0ull};
#pragma unroll
    for (int i = 0; i < 39; ++i) {
        u64 P = pack2(v[i], v[i + 1]);
#pragma unroll
        for (int m = 0; m < 8; ++m) {
            int n = i - 2 * m;
            if (n >= 0 && n < TAPS)
                fma2(A[m], W2[n <= RR ? n : 24 - n], P);
        }
    }

#pragma unroll
    for (int m = 0; m < 8; ++m) {
        float2 o = unpack2(A[m]);
        op[base + (2 * m)     * CC] = __float2half_rn(o.x);
        op[base + (2 * m + 1) * CC] = __float2half_rn(o.y);
    }
}

// ---------------- Pass 2: vertical + subtract src ---------------------------
// Thread = one half2 column pair x 8 y outputs.  Window loads front-batched.
// src/dst traffic is stream-once -> evict-first hints; tmp stays L2-resident.
__global__ void __launch_bounds__(256, 5) pass_v_kernel(const float* __restrict__ src,
                                                        const float* __restrict__ k,
                                                        float* __restrict__ dst) {
    const int PAIRS = ROWF / 2;                     // 5376 pairs per row
    const int PER_B = (HH / 8) * PAIRS;             // 344,064 threads per batch
    int tid = blockIdx.x * 256 + threadIdx.x;

    int b   = tid / PER_B;
    int rem = tid - b * PER_B;
    int yg  = rem / PAIRS;
    int fp  = rem - yg * PAIRS;
    int y0  = yg * 8;

    size_t off = (size_t)b * IMGF + 2 * (size_t)fp;
    const __half* tp = g_tmp + off;
    const float*  sp = src + off;
    float*        dp = dst + off;

    u64 W2[13];
    load_weights(k, W2);

    __half2 v[32];
    if (y0 >= RR && y0 + 19 < HH) {
#pragma unroll
        for (int s = 0; s < 32; ++s)
            v[s] = *(const __half2*)(tp + (size_t)(y0 - RR + s) * ROWF);
    } else {
        const __half2 z = __float2half2_rn(0.0f);
#pragma unroll
        for (int s = 0; s < 32; ++s) {
            int yin = y0 - RR + s;
            v[s] = (yin >= 0 && yin < HH)
                       ? *(const __half2*)(tp + (size_t)yin * ROWF)
                       : z;
        }
    }

    u64 A[8] = {0ull, 0ull, 0ull, 0ull, 0ull, 0ull, 0ull, 0ull};
#pragma unroll
    for (int s = 0; s < 32; ++s) {
        float2 f = __half22float2(v[s]);
        u64 P = pack2(f.x, f.y);
#pragma unroll
        for (int m = 0; m < 8; ++m) {
            int n = s - m;
            if (n >= 0 && n < TAPS)
                fma2(A[m], W2[n <= RR ? n : 24 - n], P);
        }
    }

#pragma unroll
    for (int m = 0; m < 8; ++m) {
        float2 o  = unpack2(A[m]);
        float2 s2 = __ldcs((const float2*)(sp + (size_t)(y0 + m) * ROWF));
        float2 r;
        r.x = o.x - s2.x;
        r.y = o.y - s2.y;
        __stcs((float2*)(dp + (size_t)(y0 + m) * ROWF), r);
    }
}

extern "C" void kernel_launch(void* const* d_in, const int* in_sizes, int n_in,
                              void* d_out, int out_size) {
    const float* src = (const float*)d_in[0];
    const float* k   = (const float*)d_in[1];
    float*       dst = (float*)d_out;

    int nthreads_h = BATCH * HH * (WW / 16) * CC;         // 1,376,256
    pass_h_kernel<<<nthreads_h / 256, 256>>>(src, k);

    int nthreads_v = BATCH * (HH / 8) * (ROWF / 2);       // 1,376,256
    pass_v_kernel<<<nthreads_v / 256, 256>>>(src, k, dst);
}